// round 14
// baseline (speedup 1.0000x reference)
#include <cuda_runtime.h>
#include <cuda_bf16.h>
#include <mma.h>
#include <cstdint>

using namespace nvcuda;

// Problem constants
#define TT 128
#define BB 64
#define HH 2048
#define LL 4
#define CC 10
#define KIN 144           // IN*ND = 48*3
#define NTB (TT*BB)       // 8192 rows
#define BH  (BB*HH)       // 131072

// GEMM tiling
#define BM 128
#define BN 128
#define BK 32
#define LDS 36            // padded smem pitch (floats); conflict-free for tf32 frags
#define STAGES 3
#define STAGE_F ((BM + BN) * LDS)
#define GEMM_SMEM_BYTES (STAGES * STAGE_F * 4)  // 110592 B -> 2 CTAs/SM

// ---------------- scratch (device globals; no allocation) ----------------
__device__ __align__(128) float g_z[NTB * HH];        // GEMM out / scan in
__device__ __align__(128) float g_h[NTB * HH];        // scan out / next GEMM in
__device__ __align__(128) float g_x144[NTB * KIN];    // tf32-rounded x
__device__ __align__(128) float g_W0r[HH * KIN];      // tf32-rounded W0
__device__ __align__(128) float g_Wfold[HH * HH];     // tf32(W * scale) for current layer
__device__ float g_d[HH];                             // d[n] = sum_k shift[k]*W[n,k]
__device__ float g_psum[BB * HH];
__device__ float g_psq [BB * HH];
__device__ float g_scale[HH];
__device__ float g_shift[HH];

__device__ __forceinline__ float to_tf32(float x) {
    float r;
    asm("cvt.rna.tf32.f32 %0, %1;" : "=f"(r) : "f"(x));
    return r;
}
__device__ __forceinline__ unsigned smem_u32(const void* p) {
    return (unsigned)__cvta_generic_to_shared(p);
}
__device__ __forceinline__ void cp_async16(unsigned dst, const void* src, int src_bytes) {
    asm volatile("cp.async.cg.shared.global [%0], [%1], 16, %2;\n"
                 :: "r"(dst), "l"(src), "r"(src_bytes));
}

// ---------------------------------------------------------------------------
// Elementwise tf32 rounding (float4 vectorized).
// ---------------------------------------------------------------------------
__global__ __launch_bounds__(256) void round_tf32_kernel(
    const float* __restrict__ in, float* __restrict__ out, int n4)
{
    int i = blockIdx.x * blockDim.x + threadIdx.x;
    if (i >= n4) return;
    float4 v = ((const float4*)in)[i];
    v.x = to_tf32(v.x); v.y = to_tf32(v.y);
    v.z = to_tf32(v.z); v.w = to_tf32(v.w);
    ((float4*)out)[i] = v;
}

// ---------------------------------------------------------------------------
// Zero the d vector (layer 0 has no BN fold).
// ---------------------------------------------------------------------------
__global__ void zero_d_kernel()
{
    int i = blockIdx.x * blockDim.x + threadIdx.x;
    if (i < HH) g_d[i] = 0.f;
}

// ---------------------------------------------------------------------------
// Fold previous layer's BN into this layer's weights:
//   Wf[n,k] = tf32(W[n,k] * scale[k]);  d[n] = sum_k shift[k] * W[n,k]
// One block per output row n. Deterministic block reduction.
// ---------------------------------------------------------------------------
__global__ __launch_bounds__(256) void fold_w_kernel(
    const float* __restrict__ W,    // [HH, HH] fp32 (original)
    float*       __restrict__ Wf,   // [HH, HH] tf32-rounded, scaled
    float*       __restrict__ dvec) // [HH]
{
    const int n   = blockIdx.x;
    const int tid = threadIdx.x;
    const float4* Wrow  = (const float4*)(W  + (size_t)n * HH);
    float4*       Wfrow = (float4*)(Wf + (size_t)n * HH);

    float acc = 0.f;
#pragma unroll 2
    for (int i = tid; i < HH / 4; i += 256) {
        float4 w  = Wrow[i];
        int k     = i * 4;
        float4 sc = *(const float4*)(g_scale + k);
        float4 sh = *(const float4*)(g_shift + k);
        acc += w.x * sh.x + w.y * sh.y + w.z * sh.z + w.w * sh.w;
        float4 o;
        o.x = to_tf32(w.x * sc.x);
        o.y = to_tf32(w.y * sc.y);
        o.z = to_tf32(w.z * sc.z);
        o.w = to_tf32(w.w * sc.w);
        Wfrow[i] = o;
    }

    __shared__ float red[256];
    red[tid] = acc;
    __syncthreads();
    for (int st = 128; st > 0; st >>= 1) {
        if (tid < st) red[tid] += red[tid + st];
        __syncthreads();
    }
    if (tid == 0) dvec[n] = red[0];
}

// ---------------------------------------------------------------------------
// TF32 GEMM, 3-stage cp.async pipeline + register double-buffered fragments.
//   C[m,n] = sum_k A[m,k] * W[n,k]
// Block tile 128x128x32, 8 warps each 64x32, wmma m16n16k8, 2 CTAs/SM.
// ---------------------------------------------------------------------------
__global__ __launch_bounds__(256, 2) void gemm_tf32_pipe(
    const float* __restrict__ A,
    const float* __restrict__ W,
    float*       __restrict__ Cmat,
    int K)
{
    extern __shared__ float sm[];

    const int bm   = blockIdx.y * BM;
    const int bn   = blockIdx.x * BN;
    const int tid  = threadIdx.x;
    const int warp = tid >> 5;
    const int wm   = warp >> 2;   // 0..1
    const int wn   = warp & 3;    // 0..3

    wmma::fragment<wmma::accumulator, 16, 16, 8, float> acc[4][2];
#pragma unroll
    for (int i = 0; i < 4; i++)
#pragma unroll
        for (int j = 0; j < 2; j++)
            wmma::fill_fragment(acc[i][j], 0.0f);

    const int kIters = (K + BK - 1) / BK;

    const int lrow0 = tid >> 3;
    const int lc4   = (tid & 7) * 4;

    auto load_stage = [&](int s, int k0) {
        float* As = sm + s * STAGE_F;
        float* Bs = As + BM * LDS;
#pragma unroll
        for (int r = 0; r < 4; r++) {
            int row = lrow0 + r * 32;
            int gk  = k0 + lc4;
            int sz  = (gk < K) ? 16 : 0;
            int gks = (gk < K) ? gk : (K - 4);
            cp_async16(smem_u32(As + row * LDS + lc4),
                       A + (size_t)(bm + row) * K + gks, sz);
            cp_async16(smem_u32(Bs + row * LDS + lc4),
                       W + (size_t)(bn + row) * K + gks, sz);
        }
    };

    // prologue: stages 0 and 1
    load_stage(0, 0);
    asm volatile("cp.async.commit_group;");
    load_stage(1, BK);
    asm volatile("cp.async.commit_group;");

    wmma::fragment<wmma::matrix_a, 16, 16, 8, wmma::precision::tf32, wmma::row_major> af[2][4];
    wmma::fragment<wmma::matrix_b, 16, 16, 8, wmma::precision::tf32, wmma::col_major> bf[2][2];

    for (int it = 0; it < kIters; it++) {
        asm volatile("cp.async.wait_group 1;");
        __syncthreads();

        int nk = it + STAGES - 1;
        if (nk < kIters) load_stage(nk % STAGES, nk * BK);
        asm volatile("cp.async.commit_group;");

        const float* As = sm + (it % STAGES) * STAGE_F;
        const float* Bs = As + BM * LDS;

        // prefetch fragments for kk=0
#pragma unroll
        for (int i = 0; i < 4; i++)
            wmma::load_matrix_sync(af[0][i], As + (wm * 64 + i * 16) * LDS + 0, LDS);
#pragma unroll
        for (int j = 0; j < 2; j++)
            wmma::load_matrix_sync(bf[0][j], Bs + (wn * 32 + j * 16) * LDS + 0, LDS);

#pragma unroll
        for (int kx = 0; kx < 4; kx++) {
            const int cur = kx & 1;
            const int nxt = cur ^ 1;
            if (kx < 3) {   // prefetch kk+1 while MMAs of kk issue
                const int kk = (kx + 1) * 8;
#pragma unroll
                for (int i = 0; i < 4; i++)
                    wmma::load_matrix_sync(af[nxt][i], As + (wm * 64 + i * 16) * LDS + kk, LDS);
#pragma unroll
                for (int j = 0; j < 2; j++)
                    wmma::load_matrix_sync(bf[nxt][j], Bs + (wn * 32 + j * 16) * LDS + kk, LDS);
            }
#pragma unroll
            for (int i = 0; i < 4; i++)
#pragma unroll
                for (int j = 0; j < 2; j++)
                    wmma::mma_sync(acc[i][j], af[cur][i], bf[cur][j], acc[i][j]);
        }
    }

#pragma unroll
    for (int i = 0; i < 4; i++)
#pragma unroll
        for (int j = 0; j < 2; j++)
            wmma::store_matrix_sync(
                Cmat + (size_t)(bm + wm * 64 + i * 16) * HH + (bn + wn * 32 + j * 16),
                acc[i][j], HH, wmma::mem_row_major);
}

// ---------------------------------------------------------------------------
// IndRNN scan: h_t = relu(z_t + (bias + d) + u * h_{t-1}).
// Writes h (tf32-rounded when rnd!=0, feeding next GEMM) and deterministic
// per-(b,h) BN partial sums computed from the UN-rounded values.
// ---------------------------------------------------------------------------
__global__ __launch_bounds__(256) void scan_kernel(
    const float* __restrict__ z,
    float*       __restrict__ hout,
    const float* __restrict__ u,
    const float* __restrict__ bias,
    const float* __restrict__ dvec,
    int rnd)
{
    int idx = blockIdx.x * blockDim.x + threadIdx.x;  // b*HH + h
    if (idx >= BH) return;
    int ch = idx & (HH - 1);
    float uu = u[ch];
    float bb = bias[ch] + dvec[ch];

    float hprev = 0.f, s = 0.f, sq = 0.f;
#pragma unroll 8
    for (int t = 0; t < TT; t++) {
        float v = z[(size_t)t * BH + idx] + bb + uu * hprev;
        v = fmaxf(v, 0.f);
        hprev = v;
        s  += v;
        sq += v * v;
        hout[(size_t)t * BH + idx] = rnd ? to_tf32(v) : v;
    }
    g_psum[idx] = s;
    g_psq[idx]  = sq;
}

// ---------------------------------------------------------------------------
// BN params: scale = gamma * rsqrt(var+eps); shift = beta - mean*scale
// ---------------------------------------------------------------------------
__global__ __launch_bounds__(256) void bn_params_kernel(
    const float* __restrict__ gamma,
    const float* __restrict__ beta)
{
    int h = blockIdx.x * blockDim.x + threadIdx.x;
    if (h >= HH) return;
    float s = 0.f, q = 0.f;
#pragma unroll 4
    for (int b = 0; b < BB; b++) {
        s += g_psum[b * HH + h];
        q += g_psq [b * HH + h];
    }
    const float inv_n = 1.0f / (float)(TT * BB);
    float mean = s * inv_n;
    float var  = q * inv_n - mean * mean;
    float sc   = gamma[h] * rsqrtf(var + 1e-5f);
    g_scale[h] = sc;
    g_shift[h] = beta[h] - mean * sc;
}

// ---------------------------------------------------------------------------
// Final projection with layer-3 BN applied on the fly:
//   out[b,c] = sum_h (h*scale+shift) * Wlast[c,h] + blast[c]
// ---------------------------------------------------------------------------
__global__ __launch_bounds__(256) void final_kernel(
    const float* __restrict__ hlast,   // [B, H] raw scan output (layer 3)
    const float* __restrict__ Wlast,   // [C, H]
    const float* __restrict__ blast,   // [C]
    float*       __restrict__ out)     // [B, C]
{
    int b   = blockIdx.x;
    int tid = threadIdx.x;

    float acc[CC];
#pragma unroll
    for (int c = 0; c < CC; c++) acc[c] = 0.f;

    for (int h = tid; h < HH; h += 256) {
        float v = fmaf(hlast[(size_t)b * HH + h], g_scale[h], g_shift[h]);
#pragma unroll
        for (int c = 0; c < CC; c++)
            acc[c] += v * Wlast[c * HH + h];
    }

    __shared__ float sred[CC * 256];
#pragma unroll
    for (int c = 0; c < CC; c++) sred[c * 256 + tid] = acc[c];
    __syncthreads();

    for (int st = 128; st > 0; st >>= 1) {
        if (tid < st) {
#pragma unroll
            for (int c = 0; c < CC; c++)
                sred[c * 256 + tid] += sred[c * 256 + tid + st];
        }
        __syncthreads();
    }
    if (tid < CC)
        out[b * CC + tid] = sred[tid * 256] + blast[tid];
}

// ---------------------------------------------------------------------------
extern "C" void kernel_launch(void* const* d_in, const int* in_sizes, int n_in,
                              void* d_out, int out_size)
{
    const float* x      = (const float*)d_in[0];  // [8192, 144]
    const float* W0     = (const float*)d_in[1];  // [H, 144]
    const float* Ws     = (const float*)d_in[2];  // [L-1, H, H]
    const float* bs     = (const float*)d_in[3];
    const float* us     = (const float*)d_in[4];
    const float* gammas = (const float*)d_in[5];
    const float* betas  = (const float*)d_in[6];
    const float* Wlast  = (const float*)d_in[7];
    const float* blast  = (const float*)d_in[8];
    float* out = (float*)d_out;

    float *z, *h, *xr, *w0r, *wf, *dv;
    cudaGetSymbolAddress((void**)&z,   g_z);
    cudaGetSymbolAddress((void**)&h,   g_h);
    cudaGetSymbolAddress((void**)&xr,  g_x144);
    cudaGetSymbolAddress((void**)&w0r, g_W0r);
    cudaGetSymbolAddress((void**)&wf,  g_Wfold);
    cudaGetSymbolAddress((void**)&dv,  g_d);

    cudaFuncSetAttribute(gemm_tf32_pipe,
                         cudaFuncAttributeMaxDynamicSharedMemorySize,
                         GEMM_SMEM_BYTES);

    // pre-round layer-0 operands (small) to tf32
    {
        int n4;
        n4 = NTB * KIN / 4;
        round_tf32_kernel<<<(n4 + 255) / 256, 256>>>(x, xr, n4);
        n4 = HH * KIN / 4;
        round_tf32_kernel<<<(n4 + 255) / 256, 256>>>(W0, w0r, n4);
    }
    zero_d_kernel<<<HH / 256, 256>>>();

    dim3 gemm_grid(HH / BN, NTB / BM);   // (16, 64)

    for (int l = 0; l < LL; l++) {
        const float* A;
        const float* W;
        int K;
        if (l == 0) {
            A = xr; W = w0r; K = KIN;
        } else {
            // fold BN(l-1) into W_l:  Wf = tf32(W*scale), d = W @ shift
            fold_w_kernel<<<HH, 256>>>(Ws + (size_t)(l - 1) * HH * HH, wf, dv);
            A = h; W = wf; K = HH;
        }

        gemm_tf32_pipe<<<gemm_grid, 256, GEMM_SMEM_BYTES>>>(A, W, z, K);
        scan_kernel<<<BH / 256, 256>>>(z, h,
                                       us + (size_t)l * HH, bs + (size_t)l * HH,
                                       dv, (l < LL - 1) ? 1 : 0);
        bn_params_kernel<<<HH / 256, 256>>>(gammas + (size_t)l * HH, betas + (size_t)l * HH);
    }

    final_kernel<<<BB, 256>>>(h + (size_t)(TT - 1) * BH, Wlast, blast, out);
}

// round 15
// speedup vs baseline: 3.3830x; 3.3830x over previous
#include <cuda_runtime.h>
#include <cuda_fp16.h>
#include <mma.h>
#include <cstdint>

using namespace nvcuda;

// Problem constants
#define TT 128
#define BB 64
#define HH 2048
#define LL 4
#define CC 10
#define KIN 144           // IN*ND = 48*3
#define NTB (TT*BB)       // 8192 rows
#define BH  (BB*HH)       // 131072

// GEMM tiling (fp16, m16n16k16)
#define BM 128
#define BN 128
#define BK 64             // 4 kk-steps of k16 per stage
#define LDSH 72           // smem pitch in halves (64 + 8 pad); 144B rows
#define STAGES 3
#define STAGE_H ((BM + BN) * LDSH)                  // halves per stage (A then B)
#define GEMM_SMEM_BYTES (STAGES * STAGE_H * 2)      // 110592 B -> 2 CTAs/SM

// ---------------- scratch (device globals; no allocation) ----------------
__device__ __align__(128) float  g_z[NTB * HH];        // GEMM out / scan in (fp32)
__device__ __align__(128) float  g_h[NTB * HH];        // scan out (fp32, raw)
__device__ __align__(128) __half g_hH[NTB * HH];       // normalized h (fp16) -> next GEMM A
__device__ __align__(128) __half g_xH[NTB * KIN];      // fp16 x
__device__ __align__(128) __half g_W0H[HH * KIN];      // fp16 W0
__device__ __align__(128) __half g_WH[(LL - 1) * HH * HH]; // fp16 Ws
__device__ float g_psum[BB * HH];
__device__ float g_psq [BB * HH];
__device__ float g_scale[HH];
__device__ float g_shift[HH];

__device__ __forceinline__ unsigned smem_u32(const void* p) {
    return (unsigned)__cvta_generic_to_shared(p);
}
__device__ __forceinline__ void cp_async16(unsigned dst, const void* src, int src_bytes) {
    asm volatile("cp.async.cg.shared.global [%0], [%1], 16, %2;\n"
                 :: "r"(dst), "l"(src), "r"(src_bytes));
}

// ---------------------------------------------------------------------------
// fp32 -> fp16 conversion (8 elements per thread iteration, coalesced)
// ---------------------------------------------------------------------------
__global__ __launch_bounds__(256) void cvt_fp16_kernel(
    const float* __restrict__ in, __half* __restrict__ out, int n8)
{
    int i = blockIdx.x * blockDim.x + threadIdx.x;
    if (i >= n8) return;
    float4 a = ((const float4*)in)[i * 2 + 0];
    float4 b = ((const float4*)in)[i * 2 + 1];
    __half2 h0 = __floats2half2_rn(a.x, a.y);
    __half2 h1 = __floats2half2_rn(a.z, a.w);
    __half2 h2 = __floats2half2_rn(b.x, b.y);
    __half2 h3 = __floats2half2_rn(b.z, b.w);
    uint4 pack;
    pack.x = *(unsigned*)&h0; pack.y = *(unsigned*)&h1;
    pack.z = *(unsigned*)&h2; pack.w = *(unsigned*)&h3;
    ((uint4*)out)[i] = pack;
}

// ---------------------------------------------------------------------------
// BN normalize: hH = fp16(h*scale[ch] + shift[ch])   (fp32 in, fp16 out)
// ---------------------------------------------------------------------------
__global__ __launch_bounds__(256) void normalize_fp16_kernel(
    const float* __restrict__ h, __half* __restrict__ hH)
{
    int i = blockIdx.x * blockDim.x + threadIdx.x;   // float4 index
    if (i >= NTB * HH / 4) return;
    int ch = (i * 4) & (HH - 1);
    float4 v = ((const float4*)h)[i];
    v.x = fmaf(v.x, g_scale[ch + 0], g_shift[ch + 0]);
    v.y = fmaf(v.y, g_scale[ch + 1], g_shift[ch + 1]);
    v.z = fmaf(v.z, g_scale[ch + 2], g_shift[ch + 2]);
    v.w = fmaf(v.w, g_scale[ch + 3], g_shift[ch + 3]);
    __half2 h0 = __floats2half2_rn(v.x, v.y);
    __half2 h1 = __floats2half2_rn(v.z, v.w);
    uint2 pack;
    pack.x = *(unsigned*)&h0; pack.y = *(unsigned*)&h1;
    ((uint2*)(hH))[i] = pack;
}

// ---------------------------------------------------------------------------
// FP16 GEMM, 3-stage cp.async pipeline, 2 CTAs/SM.
//   C[m,n] = sum_k A[m,k] * W[n,k]   (A [M,K] fp16 row-major, W [N,K] fp16)
// Block tile 128x128x64, 8 warps each 64x32, wmma m16n16k16, fp32 accum.
// ---------------------------------------------------------------------------
__global__ __launch_bounds__(256, 2) void gemm_fp16_pipe(
    const __half* __restrict__ A,
    const __half* __restrict__ W,
    float*        __restrict__ Cmat,
    int K)
{
    extern __shared__ __half smh[];

    const int bm   = blockIdx.y * BM;
    const int bn   = blockIdx.x * BN;
    const int tid  = threadIdx.x;
    const int warp = tid >> 5;
    const int wm   = warp >> 2;   // 0..1
    const int wn   = warp & 3;    // 0..3

    wmma::fragment<wmma::accumulator, 16, 16, 16, float> acc[4][2];
#pragma unroll
    for (int i = 0; i < 4; i++)
#pragma unroll
        for (int j = 0; j < 2; j++)
            wmma::fill_fragment(acc[i][j], 0.0f);

    const int kIters = (K + BK - 1) / BK;

    // loader: tile is 128 rows x 64 halves (128B/row) = 8 chunks of 16B per row
    const int lrow0 = tid >> 3;          // rows: lrow0 + 32*r  (4 passes)
    const int lch   = (tid & 7) * 8;     // half-offset within row (8 halves/chunk)

    auto load_stage = [&](int s, int k0) {
        __half* As = smh + s * STAGE_H;
        __half* Bs = As + BM * LDSH;
#pragma unroll
        for (int r = 0; r < 4; r++) {
            int row = lrow0 + r * 32;
            int gk  = k0 + lch;
            int sz  = (gk < K) ? 16 : 0;          // zero-fill beyond K
            int gks = (gk < K) ? gk : (K - 8);    // keep address in-bounds
            cp_async16(smem_u32(As + row * LDSH + lch),
                       A + (size_t)(bm + row) * K + gks, sz);
            cp_async16(smem_u32(Bs + row * LDSH + lch),
                       W + (size_t)(bn + row) * K + gks, sz);
        }
    };

    // prologue: stages 0 and 1
    load_stage(0, 0);
    asm volatile("cp.async.commit_group;");
    load_stage(1, BK);
    asm volatile("cp.async.commit_group;");

    for (int it = 0; it < kIters; it++) {
        asm volatile("cp.async.wait_group 1;");
        __syncthreads();

        int nk = it + STAGES - 1;
        if (nk < kIters) load_stage(nk % STAGES, nk * BK);
        asm volatile("cp.async.commit_group;");

        const __half* As = smh + (it % STAGES) * STAGE_H;
        const __half* Bs = As + BM * LDSH;
#pragma unroll
        for (int kk = 0; kk < BK; kk += 16) {
            wmma::fragment<wmma::matrix_a, 16, 16, 16, __half, wmma::row_major> af[4];
            wmma::fragment<wmma::matrix_b, 16, 16, 16, __half, wmma::col_major> bf[2];
#pragma unroll
            for (int i = 0; i < 4; i++)
                wmma::load_matrix_sync(af[i], As + (wm * 64 + i * 16) * LDSH + kk, LDSH);
#pragma unroll
            for (int j = 0; j < 2; j++)
                wmma::load_matrix_sync(bf[j], Bs + (wn * 32 + j * 16) * LDSH + kk, LDSH);
#pragma unroll
            for (int i = 0; i < 4; i++)
#pragma unroll
                for (int j = 0; j < 2; j++)
                    wmma::mma_sync(acc[i][j], af[i], bf[j], acc[i][j]);
        }
    }

#pragma unroll
    for (int i = 0; i < 4; i++)
#pragma unroll
        for (int j = 0; j < 2; j++)
            wmma::store_matrix_sync(
                Cmat + (size_t)(bm + wm * 64 + i * 16) * HH + (bn + wn * 32 + j * 16),
                acc[i][j], HH, wmma::mem_row_major);
}

// ---------------------------------------------------------------------------
// IndRNN scan: h_t = relu(z_t + bias + u * h_{t-1}); deterministic BN partials.
// ---------------------------------------------------------------------------
__global__ __launch_bounds__(256) void scan_kernel(
    const float* __restrict__ z,
    float*       __restrict__ hout,
    const float* __restrict__ u,
    const float* __restrict__ bias)
{
    int idx = blockIdx.x * blockDim.x + threadIdx.x;  // b*HH + h
    if (idx >= BH) return;
    int ch = idx & (HH - 1);
    float uu = u[ch];
    float bb = bias[ch];

    float hprev = 0.f, s = 0.f, sq = 0.f;
#pragma unroll 8
    for (int t = 0; t < TT; t++) {
        float v = z[(size_t)t * BH + idx] + bb + uu * hprev;
        v = fmaxf(v, 0.f);
        hout[(size_t)t * BH + idx] = v;
        hprev = v;
        s  += v;
        sq += v * v;
    }
    g_psum[idx] = s;
    g_psq[idx]  = sq;
}

// ---------------------------------------------------------------------------
// BN params: scale = gamma * rsqrt(var+eps); shift = beta - mean*scale
// ---------------------------------------------------------------------------
__global__ __launch_bounds__(256) void bn_params_kernel(
    const float* __restrict__ gamma,
    const float* __restrict__ beta)
{
    int h = blockIdx.x * blockDim.x + threadIdx.x;
    if (h >= HH) return;
    float s = 0.f, q = 0.f;
#pragma unroll 4
    for (int b = 0; b < BB; b++) {
        s += g_psum[b * HH + h];
        q += g_psq [b * HH + h];
    }
    const float inv_n = 1.0f / (float)(TT * BB);
    float mean = s * inv_n;
    float var  = q * inv_n - mean * mean;
    float sc   = gamma[h] * rsqrtf(var + 1e-5f);
    g_scale[h] = sc;
    g_shift[h] = beta[h] - mean * sc;
}

// ---------------------------------------------------------------------------
// Final projection with layer-3 BN applied on the fly:
//   out[b,c] = sum_h (h*scale+shift) * Wlast[c,h] + blast[c]
// ---------------------------------------------------------------------------
__global__ __launch_bounds__(256) void final_kernel(
    const float* __restrict__ hlast,   // [B, H] raw fp32 scan output (layer 3)
    const float* __restrict__ Wlast,   // [C, H]
    const float* __restrict__ blast,   // [C]
    float*       __restrict__ out)     // [B, C]
{
    int b   = blockIdx.x;
    int tid = threadIdx.x;

    float acc[CC];
#pragma unroll
    for (int c = 0; c < CC; c++) acc[c] = 0.f;

    for (int h = tid; h < HH; h += 256) {
        float v = fmaf(hlast[(size_t)b * HH + h], g_scale[h], g_shift[h]);
#pragma unroll
        for (int c = 0; c < CC; c++)
            acc[c] += v * Wlast[c * HH + h];
    }

    __shared__ float sred[CC * 256];
#pragma unroll
    for (int c = 0; c < CC; c++) sred[c * 256 + tid] = acc[c];
    __syncthreads();

    for (int st = 128; st > 0; st >>= 1) {
        if (tid < st) {
#pragma unroll
            for (int c = 0; c < CC; c++)
                sred[c * 256 + tid] += sred[c * 256 + tid + st];
        }
        __syncthreads();
    }
    if (tid < CC)
        out[b * CC + tid] = sred[tid * 256] + blast[tid];
}

// ---------------------------------------------------------------------------
extern "C" void kernel_launch(void* const* d_in, const int* in_sizes, int n_in,
                              void* d_out, int out_size)
{
    const float* x      = (const float*)d_in[0];  // [8192, 144]
    const float* W0     = (const float*)d_in[1];  // [H, 144]
    const float* Ws     = (const float*)d_in[2];  // [L-1, H, H]
    const float* bs     = (const float*)d_in[3];
    const float* us     = (const float*)d_in[4];
    const float* gammas = (const float*)d_in[5];
    const float* betas  = (const float*)d_in[6];
    const float* Wlast  = (const float*)d_in[7];
    const float* blast  = (const float*)d_in[8];
    float* out = (float*)d_out;

    float  *z, *h;
    __half *hH, *xH, *w0H, *wH;
    cudaGetSymbolAddress((void**)&z,   g_z);
    cudaGetSymbolAddress((void**)&h,   g_h);
    cudaGetSymbolAddress((void**)&hH,  g_hH);
    cudaGetSymbolAddress((void**)&xH,  g_xH);
    cudaGetSymbolAddress((void**)&w0H, g_W0H);
    cudaGetSymbolAddress((void**)&wH,  g_WH);

    cudaFuncSetAttribute(gemm_fp16_pipe,
                         cudaFuncAttributeMaxDynamicSharedMemorySize,
                         GEMM_SMEM_BYTES);

    // convert GEMM operands to fp16 (rne; ulp identical to tf32)
    {
        int n8;
        n8 = NTB * KIN / 8;
        cvt_fp16_kernel<<<(n8 + 255) / 256, 256>>>(x, xH, n8);
        n8 = HH * KIN / 8;
        cvt_fp16_kernel<<<(n8 + 255) / 256, 256>>>(W0, w0H, n8);
        n8 = (LL - 1) * HH * HH / 8;
        cvt_fp16_kernel<<<(n8 + 255) / 256, 256>>>(Ws, wH, n8);
    }

    dim3 gemm_grid(HH / BN, NTB / BM);   // (16, 64)
    const int norm_blocks = (NTB * HH / 4 + 255) / 256;

    for (int l = 0; l < LL; l++) {
        const __half* A = (l == 0) ? xH : hH;
        const __half* W = (l == 0) ? w0H : (wH + (size_t)(l - 1) * HH * HH);
        int K = (l == 0) ? KIN : HH;

        gemm_fp16_pipe<<<gemm_grid, 256, GEMM_SMEM_BYTES>>>(A, W, z, K);
        scan_kernel<<<BH / 256, 256>>>(z, h, us + (size_t)l * HH, bs + (size_t)l * HH);
        bn_params_kernel<<<HH / 256, 256>>>(gammas + (size_t)l * HH, betas + (size_t)l * HH);
        if (l < LL - 1)
            normalize_fp16_kernel<<<norm_blocks, 256>>>(h, hH);
        // layer 3: final_kernel applies BN on the fly
    }

    final_kernel<<<BB, 256>>>(h + (size_t)(TT - 1) * BH, Wlast, blast, out);
}